// round 4
// baseline (speedup 1.0000x reference)
#include <cuda_runtime.h>

#define N 1024
#define D 64
#define H 8
#define IDXE 64
#define NSPLIT 32     // spmm m-splits
#define KC 32         // m-chunk per block
#define NT 256        // n-tile for spmm
#define TG_SPLIT 8
#define PADA 260
#define PADU 68
#define PADW 68
#define PADX 66

typedef unsigned long long ull;

// ---------------- f32x2 helpers ----------------
__device__ __forceinline__ ull pk2(float lo, float hi) {
    ull r; asm("mov.b64 %0, {%1,%2};" : "=l"(r) : "f"(lo), "f"(hi)); return r;
}
__device__ __forceinline__ ull dup2(float x) {
    ull r; asm("mov.b64 %0, {%1,%1};" : "=l"(r) : "f"(x)); return r;
}
__device__ __forceinline__ ull fma2(ull a, ull b, ull c) {
    ull d; asm("fma.rn.f32x2 %0, %1, %2, %3;" : "=l"(d) : "l"(a), "l"(b), "l"(c)); return d;
}
__device__ __forceinline__ ull add2(ull a, ull b) {
    ull d; asm("add.rn.f32x2 %0, %1, %2;" : "=l"(d) : "l"(a), "l"(b)); return d;
}
__device__ __forceinline__ ull mul2(ull a, ull b) {
    ull d; asm("mul.rn.f32x2 %0, %1, %2;" : "=l"(d) : "l"(a), "l"(b)); return d;
}
__device__ __forceinline__ ull relu2(ull v) {
    float lo, hi;
    asm("mov.b64 {%0,%1}, %2;" : "=f"(lo), "=f"(hi) : "l"(v));
    lo = fmaxf(lo, 0.f); hi = fmaxf(hi, 0.f);
    return pk2(lo, hi);
}
__device__ __forceinline__ void unpk2(ull v, float& lo, float& hi) {
    asm("mov.b64 {%0,%1}, %2;" : "=f"(lo), "=f"(hi) : "l"(v));
}

// ---------------- static scratch ----------------
__device__ float g_a[N * N];
__device__ float g_ad[N * N];
__device__ float g_rowpb[2][N][H];   // row-proj + b1
__device__ float g_colT[2][H][N];    // col-proj, transposed
__device__ float g_tgp[TG_SPLIT][N];
__device__ float g_xbuf[2][N * D];
__device__ float g_part[NSPLIT][N * D];

// ---------------- projections ----------------
__global__ void proj_kernel(const float* __restrict__ idx_emb,
                            const float* __restrict__ W1,
                            const float* __restrict__ b1) {
    int id = blockIdx.x * blockDim.x + threadIdx.x;   // 32768 threads
    int h  = id & 7;
    int s  = (id >> 3) & 1;
    int rc = (id >> 4) & 1;
    int n  = id >> 5;
    const float* w = W1 + s * (H * 129) + h * 129 + 1 + rc * IDXE;
    const float* e = idx_emb + n * IDXE;
    float acc = 0.f;
#pragma unroll 16
    for (int k = 0; k < IDXE; k++) acc = fmaf(e[k], w[k], acc);
    if (rc == 0) g_rowpb[s][n][h] = acc + b1[s * H + h];
    else         g_colT[s][h][n]  = acc;
}

// ---------------- tg partials ----------------
__global__ void tg_kernel(const float* __restrict__ t_grad) {
    int n = blockIdx.x * 256 + threadIdx.x;
    int s = blockIdx.y;
    const int R = N / TG_SPLIT;
    float acc = 0.f;
    for (int m = s * R; m < (s + 1) * R; m++) acc += t_grad[m * N + n];
    g_tgp[s][n] = acc;
}

// ---------------- edge MLPs (packed pair of edges per thread) ----------------
__device__ __forceinline__ ull mlp2(ull a2, const ull* __restrict__ wa,
                                    const ull* __restrict__ rc,
                                    const ull* __restrict__ W2,
                                    const ull* __restrict__ b2,
                                    const ull* __restrict__ W3, ull b3v) {
    ull h1[H];
#pragma unroll
    for (int h = 0; h < H; h++)
        h1[h] = relu2(fma2(a2, wa[h], rc[h]));
    ull out = b3v;
#pragma unroll
    for (int k = 0; k < H; k++) {
        ull t = b2[k];
#pragma unroll
        for (int h = 0; h < H; h++) t = fma2(W2[k * H + h], h1[h], t);
        out = fma2(W3[k], relu2(t), out);
    }
    return out;
}

__global__ void __launch_bounds__(256) msg_kernel(const float* __restrict__ adj,
                           const float* __restrict__ adjd,
                           const float* __restrict__ W1,
                           const float* __restrict__ W2,
                           const float* __restrict__ b2,
                           const float* __restrict__ W3,
                           const float* __restrict__ b3) {
    __shared__ ull wa2[2][H], W2d[2][H * H], b2d[2][H], W3d[2][H], b3d[2];
    __shared__ float rcn[2][8][H];
    __shared__ ull ccm2[2][H][32];
    int tid = threadIdx.x;
    int mb = blockIdx.x * 64, nb = blockIdx.y * 8;

    if (tid < 16) {
        int s = tid >> 3, h = tid & 7;
        wa2[s][h] = dup2(W1[s * (H * 129) + h * 129]);
        b2d[s][h] = dup2(b2[tid]);
        W3d[s][h] = dup2(W3[tid]);
    }
    if (tid < 2) b3d[tid] = dup2(b3[tid]);
    if (tid >= 32 && tid < 160) {
        int i = tid - 32;
        W2d[i >> 6][i & 63] = dup2(W2[i]);
    }
    if (tid < 128) {
        int s = tid >> 6, r = (tid >> 3) & 7, h = tid & 7;
        rcn[s][r][h] = g_rowpb[s][nb + r][h];
    }
    for (int i = tid; i < 512; i += 256) {
        int s = i >> 8, h = (i >> 5) & 7, mp = i & 31;
        float2 c = *(const float2*)(&g_colT[s][h][mb + 2 * mp]);
        ccm2[s][h][mp] = pk2(c.x, c.y);
    }
    __syncthreads();

    int mp = tid & 31, nloc = tid >> 5;
    int m0 = mb + 2 * mp, n = nb + nloc;
    float2 av  = *(const float2*)(adj  + n * N + m0);
    float2 adv = *(const float2*)(adjd + n * N + m0);

    {
        ull rc2[H];
#pragma unroll
        for (int h = 0; h < H; h++)
            rc2[h] = add2(dup2(rcn[0][nloc][h]), ccm2[0][h][mp]);
        ull o = mlp2(pk2(av.x, av.y), wa2[0], rc2, W2d[0], b2d[0], W3d[0], b3d[0]);
        float lo, hi; unpk2(o, lo, hi);
        *(float2*)(g_a + n * N + m0) = make_float2(lo, hi);
    }
    {
        ull rc2[H];
#pragma unroll
        for (int h = 0; h < H; h++)
            rc2[h] = add2(dup2(rcn[1][nloc][h]), ccm2[1][h][mp]);
        ull o = mlp2(pk2(adv.x, adv.y), wa2[1], rc2, W2d[1], b2d[1], W3d[1], b3d[1]);
        float lo, hi; unpk2(o, lo, hi);
        *(float2*)(g_ad + n * N + m0) = make_float2(lo, hi);
    }
}

// ---------------- fused: u-slice projection + 4-way product ----------------
// Block (bx, by): n-tile [bx*NT, +NT), m-slice [by*KC, +KC).
// Phase 1: stage a/ad tiles (both orientations) + x slice.
// Phase 2: compute u_q = x_slice @ W[l][q] for q=0..3 into smem.
// Phase 3: register-tiled f32x2 product; write partial.
__global__ void __launch_bounds__(512, 1) spmm_kernel(const float* __restrict__ y,
                                                      const float* __restrict__ gnn_W,
                                                      int layer) {
    extern __shared__ float sm[];
    float* a_ds = sm;                    // [KC][PADA]
    float* a_ts = a_ds + KC * PADA;
    float* d_ds = a_ts + KC * PADA;
    float* d_ts = d_ds + KC * PADA;
    float* u0s  = d_ts + KC * PADA;      // [KC][PADU]
    float* u1s  = u0s + KC * PADU;
    float* u2s  = u1s + KC * PADU;
    float* u3s  = u2s + KC * PADU;
    float* Ws   = u3s + KC * PADU;       // [64][PADW]
    float* xs   = Ws + 64 * PADW;        // [KC][PADX]

    int tid = threadIdx.x;
    int n0 = blockIdx.x * NT;
    int m0 = blockIdx.y * KC;
    const float* x = (layer == 0) ? y : g_xbuf[layer - 1];
    const float* Wbase = gnn_W + layer * 5 * 4096;

    // ---- stage a/ad tiles ----
    for (int idx = tid; idx < NT * KC; idx += 512) {
        int i = idx >> 5, j = idx & 31;
        a_ds[j * PADA + i] = g_a[(n0 + i) * N + m0 + j];
        d_ds[j * PADA + i] = g_ad[(n0 + i) * N + m0 + j];
    }
    for (int idx = tid; idx < NT * KC; idx += 512) {
        int j = idx >> 8, i = idx & 255;
        a_ts[j * PADA + i] = g_a[(m0 + j) * N + n0 + i];
        d_ts[j * PADA + i] = g_ad[(m0 + j) * N + n0 + i];
    }
    // ---- stage x slice ----
    for (int idx = tid; idx < KC * D; idx += 512) {
        int r = idx >> 6, k = idx & 63;
        xs[r * PADX + k] = x[(m0 + r) * D + k];
    }
    __syncthreads();

    // ---- compute u_q slices ----
    {
        int r = tid >> 4;            // 0..31
        int cc = (tid & 15) * 4;     // 0..60
        float* uout[4] = {u0s, u1s, u2s, u3s};
#pragma unroll
        for (int q = 0; q < 4; q++) {
            const float* W = Wbase + q * 4096;
            for (int idx = tid; idx < 4096; idx += 512)
                Ws[(idx >> 6) * PADW + (idx & 63)] = W[idx];
            __syncthreads();
            ull acc0 = 0ull, acc1 = 0ull;
#pragma unroll 16
            for (int k = 0; k < 64; k++) {
                ull xv = dup2(xs[r * PADX + k]);
                ulonglong2 wv = *(const ulonglong2*)(Ws + k * PADW + cc);
                acc0 = fma2(xv, wv.x, acc0);
                acc1 = fma2(xv, wv.y, acc1);
            }
            ulonglong2 v; v.x = acc0; v.y = acc1;
            *(ulonglong2*)(uout[q] + r * PADU + cc) = v;
            __syncthreads();
        }
    }

    // ---- main 4-way product ----
    int tr = tid >> 4;        // 0..31 -> rows i0 = tr*8
    int tc = tid & 15;        // 0..15 -> cols c0 = tc*4
    int i0 = tr * 8, c0 = tc * 4;

    ull acc[8][2];
#pragma unroll
    for (int i = 0; i < 8; i++) { acc[i][0] = 0ull; acc[i][1] = 0ull; }

    for (int j = 0; j < KC; j++) {
        ulonglong2 u0p = *(const ulonglong2*)(u0s + j * PADU + c0);
        ulonglong2 u1p = *(const ulonglong2*)(u1s + j * PADU + c0);
        ulonglong2 u2p = *(const ulonglong2*)(u2s + j * PADU + c0);
        ulonglong2 u3p = *(const ulonglong2*)(u3s + j * PADU + c0);
        float aD[8], aT[8], bD[8], bT[8];
        *(float4*)(aD)     = *(const float4*)(a_ds + j * PADA + i0);
        *(float4*)(aD + 4) = *(const float4*)(a_ds + j * PADA + i0 + 4);
        *(float4*)(aT)     = *(const float4*)(a_ts + j * PADA + i0);
        *(float4*)(aT + 4) = *(const float4*)(a_ts + j * PADA + i0 + 4);
        *(float4*)(bD)     = *(const float4*)(d_ds + j * PADA + i0);
        *(float4*)(bD + 4) = *(const float4*)(d_ds + j * PADA + i0 + 4);
        *(float4*)(bT)     = *(const float4*)(d_ts + j * PADA + i0);
        *(float4*)(bT + 4) = *(const float4*)(d_ts + j * PADA + i0 + 4);
#pragma unroll
        for (int i = 0; i < 8; i++) {
            ull aDd = dup2(aD[i]), aTd = dup2(aT[i]);
            ull bDd = dup2(bD[i]), bTd = dup2(bT[i]);
            acc[i][0] = fma2(aDd, u0p.x, fma2(aTd, u1p.x, fma2(bDd, u2p.x, fma2(bTd, u3p.x, acc[i][0]))));
            acc[i][1] = fma2(aDd, u0p.y, fma2(aTd, u1p.y, fma2(bDd, u2p.y, fma2(bTd, u3p.y, acc[i][1]))));
        }
    }

    float* outp = g_part[blockIdx.y];
#pragma unroll
    for (int i = 0; i < 8; i++) {
        ulonglong2 v; v.x = acc[i][0]; v.y = acc[i][1];
        *(ulonglong2*)(outp + (n0 + i0 + i) * D + c0) = v;
    }
}

// ---------------- reduce: x@W4 + bias + sum partials (+relu) ----------------
__global__ void __launch_bounds__(256) reduce_kernel(const float* __restrict__ y,
                                                     const float* __restrict__ gnn_W,
                                                     const float* __restrict__ gnn_b,
                                                     int layer) {
    __shared__ float Ws[64 * PADW];
    __shared__ float xs[8 * PADX];
    int tid = threadIdx.x;
    int n0 = blockIdx.x * 8;            // grid 128
    const float* x = (layer == 0) ? y : g_xbuf[layer - 1];
    const float* W = gnn_W + (layer * 5 + 4) * 4096;

    for (int idx = tid; idx < 4096; idx += 256)
        Ws[(idx >> 6) * PADW + (idx & 63)] = W[idx];
    for (int idx = tid; idx < 8 * D; idx += 256) {
        int r = idx >> 6, k = idx & 63;
        xs[r * PADX + k] = x[(n0 + r) * D + k];
    }
    __syncthreads();

    int r = tid >> 5;                    // 0..7
    int cc = (tid & 31) * 2;             // 0..62
    ull acc = pk2(gnn_b[layer * D + cc], gnn_b[layer * D + cc + 1]);
#pragma unroll 16
    for (int k = 0; k < 64; k++) {
        ull xv = dup2(xs[r * PADX + k]);
        ull wv = *(const ull*)(Ws + k * PADW + cc);
        acc = fma2(xv, wv, acc);
    }
    int off = (n0 + r) * D + cc;
#pragma unroll
    for (int s = 0; s < NSPLIT; s++)
        acc = add2(acc, *(const ull*)(g_part[s] + off));
    acc = relu2(acc);
    *(ull*)(g_xbuf[layer] + off) = acc;
}

// ---------------- final: x@W4 + bias + partials, scale by tg ----------------
__global__ void __launch_bounds__(256) final_kernel(float* __restrict__ out,
                                                    const float* __restrict__ gnn_W,
                                                    const float* __restrict__ gnn_b) {
    __shared__ float Ws[64 * PADW];
    __shared__ float xs[8 * PADX];
    int tid = threadIdx.x;
    int n0 = blockIdx.x * 8;
    const float* x = g_xbuf[1];
    const float* W = gnn_W + (2 * 5 + 4) * 4096;

    for (int idx = tid; idx < 4096; idx += 256)
        Ws[(idx >> 6) * PADW + (idx & 63)] = W[idx];
    for (int idx = tid; idx < 8 * D; idx += 256) {
        int r = idx >> 6, k = idx & 63;
        xs[r * PADX + k] = x[(n0 + r) * D + k];
    }
    __syncthreads();

    int r = tid >> 5;
    int cc = (tid & 31) * 2;
    ull acc = pk2(gnn_b[2 * D + cc], gnn_b[2 * D + cc + 1]);
#pragma unroll 16
    for (int k = 0; k < 64; k++) {
        ull xv = dup2(xs[r * PADX + k]);
        ull wv = *(const ull*)(Ws + k * PADW + cc);
        acc = fma2(xv, wv, acc);
    }
    int off = (n0 + r) * D + cc;
#pragma unroll
    for (int s = 0; s < NSPLIT; s++)
        acc = add2(acc, *(const ull*)(g_part[s] + off));
    float tg = 0.f;
#pragma unroll
    for (int s = 0; s < TG_SPLIT; s++) tg += g_tgp[s][n0 + r];
    tg *= (1.0f / N);
    acc = mul2(acc, dup2(tg));
    *(ull*)(out + off) = acc;
}

// ---------------- launch ----------------
extern "C" void kernel_launch(void* const* d_in, const int* in_sizes, int n_in,
                              void* d_out, int out_size) {
    const float* y       = (const float*)d_in[0];
    const float* adj     = (const float*)d_in[1];
    const float* adjd    = (const float*)d_in[2];
    const float* t_grad  = (const float*)d_in[3];
    const float* idx_emb = (const float*)d_in[4];
    const float* msg_W1  = (const float*)d_in[5];
    const float* msg_b1  = (const float*)d_in[6];
    const float* msg_W2  = (const float*)d_in[7];
    const float* msg_b2  = (const float*)d_in[8];
    const float* msg_W3  = (const float*)d_in[9];
    const float* msg_b3  = (const float*)d_in[10];
    const float* gnn_W   = (const float*)d_in[11];
    const float* gnn_b   = (const float*)d_in[12];
    float* out = (float*)d_out;

    const int spmm_smem = (4 * KC * PADA + 4 * KC * PADU + 64 * PADW + KC * PADX)
                          * (int)sizeof(float);   // 193,792 B
    cudaFuncSetAttribute(spmm_kernel, cudaFuncAttributeMaxDynamicSharedMemorySize, spmm_smem);

    // fork: tg on side stream, overlapped with proj->msg
    cudaStream_t s2;
    cudaEvent_t eF, eJ;
    cudaStreamCreateWithFlags(&s2, cudaStreamNonBlocking);
    cudaEventCreateWithFlags(&eF, cudaEventDisableTiming);
    cudaEventCreateWithFlags(&eJ, cudaEventDisableTiming);

    cudaEventRecord(eF, 0);
    cudaStreamWaitEvent(s2, eF, 0);
    tg_kernel<<<dim3(4, TG_SPLIT), 256, 0, s2>>>(t_grad);
    cudaEventRecord(eJ, s2);

    proj_kernel<<<128, 256>>>(idx_emb, msg_W1, msg_b1);
    msg_kernel<<<dim3(16, 128), 256>>>(adj, adjd, msg_W1, msg_W2, msg_b2, msg_W3, msg_b3);

    for (int l = 0; l < 3; l++) {
        spmm_kernel<<<dim3(N / NT, NSPLIT), 512, spmm_smem>>>(y, gnn_W, l);
        if (l < 2) {
            reduce_kernel<<<128, 256>>>(y, gnn_W, gnn_b, l);
        } else {
            cudaStreamWaitEvent(0, eJ, 0);
            final_kernel<<<128, 256>>>(out, gnn_W, gnn_b);
        }
    }
}